// round 15
// baseline (speedup 1.0000x reference)
#include <cuda_runtime.h>
#include <cstdint>

#define T_LEN 2048
#define BATCH 32
#define HID   256
#define G3    768
#define SBLK  64            // 8 scan clusters x 8 CTAs
#define NTOT  136           // 17 clusters total (fits 70/78 die split)
#define NWORK 72
#define NTILE 8192

typedef unsigned long long ull;

// smem float offsets (scan CTA)
#define WB_OFF 0            // L1 weights [512 k][64 pc]            = 32768
#define HS_OFF 32768        // slots [2][h1:256x4 | h0:256x4]       = 4096
#define RA_OFF 36864        // L0 partials      [4q][32l][2pc][4r]  = 1024
#define RT_OFF 37888        // L1-tail partials [4q][32l][2pc][4r]  = 1024
#define RB_OFF 38912        // L1-main partials [4q][32l][2pc][4r]  = 1024
#define SG_OFF 39936        // staging [2 layer][32 j][4 r]         = 256
#define FL_OFF 40192        // flagS[8] (u32) + pad
#define SMEM_FLOATS 40224
#define SMEM_BYTES  (SMEM_FLOATS * 4)

__device__ float g_X[(size_t)T_LEN * BATCH * 512];   // [m=t*32+b][c 512]
__device__ unsigned g_tcnt[T_LEN / 2];               // 8 tiles per bx per run
__device__ unsigned g_run;                           // epoch

// ---------------------------------------------------------------------------
__device__ __forceinline__ ull pack2(float v) {
    ull r; asm("mov.b64 %0, {%1, %1};" : "=l"(r) : "f"(v)); return r;
}
__device__ __forceinline__ void fma2(ull& d, ull a, ull b) {
    asm("fma.rn.f32x2 %0, %1, %2, %0;" : "+l"(d) : "l"(a), "l"(b));
}
__device__ __forceinline__ void unpack2(ull v, float& lo, float& hi) {
    asm("mov.b64 {%0, %1}, %2;" : "=f"(lo), "=f"(hi) : "l"(v));
}
__device__ __forceinline__ uint32_t smem_u32(const void* p) {
    uint32_t a;
    asm("{ .reg .u64 t; cvta.to.shared.u64 t, %1; cvt.u32.u64 %0, t; }"
        : "=r"(a) : "l"(p));
    return a;
}
__device__ __forceinline__ uint32_t mapa_u32(uint32_t local, uint32_t rank) {
    uint32_t r;
    asm("mapa.shared::cluster.u32 %0, %1, %2;" : "=r"(r) : "r"(local), "r"(rank));
    return r;
}
__device__ __forceinline__ void stv4_cluster(uint32_t a, float4 v) {
    asm volatile("st.shared::cluster.v4.f32 [%0], {%1,%2,%3,%4};"
                 :: "r"(a), "f"(v.x), "f"(v.y), "f"(v.z), "f"(v.w) : "memory");
}
__device__ __forceinline__ void st_flag_release(uint32_t a, unsigned v) {
    asm volatile("st.release.cluster.shared::cluster.u32 [%0], %1;"
                 :: "r"(a), "r"(v) : "memory");
}
__device__ __forceinline__ void spin_flag(uint32_t a, unsigned target) {
    unsigned v;
    do {
        asm volatile("ld.acquire.cluster.shared::cta.u32 %0, [%1];"
                     : "=r"(v) : "r"(a) : "memory");
    } while ((int)(v - target) < 0);
}
__device__ __forceinline__ void poll_ge(const unsigned* addr, unsigned target) {
    unsigned v;
    do {
        asm volatile("ld.acquire.gpu.global.u32 %0, [%1];"
                     : "=r"(v) : "l"(addr) : "memory");
    } while ((int)(v - target) < 0);
}
__device__ __forceinline__ void cluster_bar() {
    asm volatile("barrier.cluster.arrive.aligned;" ::: "memory");
    asm volatile("barrier.cluster.wait.aligned;" ::: "memory");
}

// ---------------------------------------------------------------------------
// GEMM worker: grid-strided 64x64x256 tiles; g_X = input @ Wih0[:,:512] + b0
// ---------------------------------------------------------------------------
__device__ void gemm_worker(int wb, const float* __restrict__ A,
                            const float* __restrict__ W,
                            const float* __restrict__ bias,
                            float* smem, int Lmax)
{
    float (*As)[65] = (float(*)[65])smem;
    float (*Bs)[64] = (float(*)[64])(smem + 32 * 65);

    const int tid = threadIdx.x;
    const int tx  = tid & 15;
    const int ty  = tid >> 4;
    const int ar  = tid >> 2;
    const int ak  = (tid & 3) * 8;
    const int bk  = tid >> 3;
    const int bc  = (tid & 7) * 8;

    for (int n = wb; n < NTILE; n += NWORK) {
        const int bx = n >> 3;
        if (2 * bx >= Lmax) break;
        const int m0 = bx * 64;
        const int n0 = (n & 7) * 64;

        ull acc2[4][2];
#pragma unroll
        for (int i = 0; i < 4; i++) { acc2[i][0] = 0ull; acc2[i][1] = 0ull; }

        for (int k0 = 0; k0 < 256; k0 += 32) {
            float4 a0  = *(const float4*)&A[(size_t)(m0 + ar) * 256 + k0 + ak];
            float4 a1  = *(const float4*)&A[(size_t)(m0 + ar) * 256 + k0 + ak + 4];
            float4 b0v = *(const float4*)&W[(size_t)(k0 + bk) * G3 + n0 + bc];
            float4 b1v = *(const float4*)&W[(size_t)(k0 + bk) * G3 + n0 + bc + 4];

            As[ak + 0][ar] = a0.x; As[ak + 1][ar] = a0.y;
            As[ak + 2][ar] = a0.z; As[ak + 3][ar] = a0.w;
            As[ak + 4][ar] = a1.x; As[ak + 5][ar] = a1.y;
            As[ak + 6][ar] = a1.z; As[ak + 7][ar] = a1.w;
            *(float4*)&Bs[bk][bc]     = b0v;
            *(float4*)&Bs[bk][bc + 4] = b1v;
            __syncthreads();

#pragma unroll
            for (int kk = 0; kk < 32; kk++) {
                const ulonglong2 bq = *(const ulonglong2*)&Bs[kk][ty * 4];
#pragma unroll
                for (int ri = 0; ri < 4; ri++) {
                    const ull av = pack2(As[kk][tx * 4 + ri]);
                    fma2(acc2[ri][0], bq.x, av);
                    fma2(acc2[ri][1], bq.y, av);
                }
            }
            __syncthreads();
        }

        const float4 bv = *(const float4*)&bias[n0 + ty * 4];
#pragma unroll
        for (int ri = 0; ri < 4; ri++) {
            float4 v;
            unpack2(acc2[ri][0], v.x, v.y);
            unpack2(acc2[ri][1], v.z, v.w);
            v.x += bv.x; v.y += bv.y; v.z += bv.z; v.w += bv.w;
            *(float4*)&g_X[(size_t)(m0 + tx * 4 + ri) * 512 + n0 + ty * 4] = v;
        }

        __threadfence();
        __syncthreads();
        if (tid == 0) {
            asm volatile("red.release.gpu.global.add.u32 [%0], %1;"
                         :: "l"(&g_tcnt[bx]), "r"(1u) : "memory");
        }
    }
}

// ---------------------------------------------------------------------------
// ONE kernel, grid 136, cluster 8.
// blocks 0..63: scan. cluster = domain (4 rows); CTA owns 32 h-cols, both layers.
//   Round i: warps 4-7: L0 dot (K=256) + L1-tail dot (staged k 384..511);
//            warps 0-3: L1-main dot (staged k 0..383). All gates; then each CTA
//   pushes its 128 new h values into all 8 peers' smem slot (i&1) via
//   st.shared::cluster, fence, st.release of a monotonic smem flag.
//   Slot layout: [h1(256x4) | h0(256x4)]; L1 staged vec is LINEAR in k.
// blocks 64..135: gemm workers.
// ---------------------------------------------------------------------------
__global__ __launch_bounds__(256, 1) __cluster_dims__(8, 1, 1)
void fused_all(
    const float* __restrict__ input,
    const float* __restrict__ Whh0,
    const float* __restrict__ Whh1,
    const float* __restrict__ Wih0,
    const float* __restrict__ Wih1,
    const float* __restrict__ b0,
    const float* __restrict__ b1,
    const int*   __restrict__ length,
    float* __restrict__ out1,
    float* __restrict__ hn)
{
    extern __shared__ float smem[];
    const int bid = blockIdx.x;
    const int tid = threadIdx.x;

    int Lmax = 0;
#pragma unroll 8
    for (int r = 0; r < BATCH; r++) Lmax = max(Lmax, length[r]);

    if (bid >= SBLK) {
        gemm_worker(bid - SBLK, input, Wih0, b0, smem, Lmax);
        return;
    }

    const int d    = bid >> 3;
    const int rank = bid & 7;
    const int c0   = rank * 32;
    const int dom4 = d * 4;

    int Ld = 0;
#pragma unroll
    for (int r = 0; r < 4; r++) Ld = max(Ld, length[dom4 + r]);

    const unsigned R  = *(volatile unsigned*)&g_run;
    const unsigned tb = R * 8u;

    // ---- init ----
    for (int i = tid; i < 4096; i += 256) smem[HS_OFF + i] = 0.f;
    smem[SG_OFF + tid] = 0.f;
    if (tid < 8) ((unsigned*)(smem + FL_OFF))[tid] = 0u;
    for (int idx = tid; idx < 32768; idx += 256) {
        const int k = idx >> 6, p = idx & 63;
        const int col = (p < 32) ? (c0 + p) : (256 + c0 + p - 32);
        smem[WB_OFF + idx] = (k < 256) ? Whh1[(size_t)k * G3 + col]
                                       : Wih1[(size_t)(k - 256) * G3 + col];
    }
    __syncthreads();
    cluster_bar();                         // flags/slots visible before any push

    const uint32_t sb = smem_u32(smem);
    uint32_t rbase[8];
#pragma unroll
    for (int p = 0; p < 8; p++) rbase[p] = mapa_u32(sb, p);

    const int wid  = tid >> 5;
    const int lane = tid & 31;
    const int pp0  = 2 * lane;             // local precol pair pp0, pp0+1
    const int colA0 = (pp0 < 32) ? (c0 + pp0) : (256 + c0 + pp0 - 32);

    // A weights (warps 4-7): L0, 2 precols x 64 k in registers
    float wA0[64], wA1[64];
    if (wid >= 4) {
        const int q = wid - 4;
#pragma unroll
        for (int kk = 0; kk < 64; kk++) {
            wA0[kk] = Whh0[(size_t)(q * 64 + kk) * G3 + colA0];
            wA1[kk] = Whh0[(size_t)(q * 64 + kk) * G3 + colA0 + 1];
        }
    }

    // gate identity: 256 gate values (2 layers x 32 cols x 4 rows)
    const int glayer = tid >> 7;           // 0 -> L0 (tid<128), 1 -> L1
    const int gj = (tid >> 2) & 31;
    const int gr = tid & 3;
    const int glen = length[dom4 + gr];
    float gbh = 0.f, gbt = 0.f;
    if (glayer) { gbh = b1[c0 + gj]; gbt = b1[256 + c0 + gj]; }
    float hcur = 0.f;
    int rdy = 0;

    for (int i = 0; i <= Ld; i++) {
        const bool act0 = (i < Ld);
        const bool act1 = (i >= 1);
        const int rs = (i + 1) & 1;        // read slot ((i-1)&1)
        const int ws = i & 1;              // write slot

        // ---- wait: local smem flags from all 8 producers >= i ----
        if (i > 0 && tid < 8)
            spin_flag(sb + (uint32_t)(FL_OFF + tid) * 4, (unsigned)i);
        if (tid == 8 && act0 && (i >> 1) >= rdy) {
            poll_ge(&g_tcnt[i >> 1], tb + 8u);
            rdy = (i >> 1) + 1;
        }
        __syncthreads();

        // ---- L0 x-term prefetch (L0 gate threads) ----
        float xh = 0.f, xt = 0.f;
        if (!glayer && act0) {
            const size_t m = (size_t)i * BATCH + dom4 + gr;
            xh = __ldg(&g_X[m * 512 + c0 + gj]);
            xt = __ldg(&g_X[m * 512 + 256 + c0 + gj]);
        }

        // ---- dots ----
        const float* slot = smem + HS_OFF + rs * 2048;
        if (wid < 4) {
            if (act1) {                    // L1 main: staged k [wid*96, +96)
                const int kb = wid * 96;
                ull a00 = 0ull, a01 = 0ull, a10 = 0ull, a11 = 0ull;
#pragma unroll 24
                for (int kk = 0; kk < 96; kk++) {
                    const int k = kb + kk;
                    const ulonglong2 hv = *(const ulonglong2*)&slot[k * 4];
                    const float2 wv = *(const float2*)&smem[WB_OFF + k * 64 + pp0];
                    const ull w0 = pack2(wv.x), w1 = pack2(wv.y);
                    fma2(a00, hv.x, w0); fma2(a01, hv.y, w0);
                    fma2(a10, hv.x, w1); fma2(a11, hv.y, w1);
                }
                ulonglong2 s0; s0.x = a00; s0.y = a01;
                ulonglong2 s1; s1.x = a10; s1.y = a11;
                *(ulonglong2*)&smem[RB_OFF + ((wid * 32 + lane) * 2 + 0) * 4] = s0;
                *(ulonglong2*)&smem[RB_OFF + ((wid * 32 + lane) * 2 + 1) * 4] = s1;
            }
        } else {
            const int q = wid - 4;
            if (act0) {                    // L0: h0 part of slot (offset 1024)
                ull a00 = 0ull, a01 = 0ull, a10 = 0ull, a11 = 0ull;
#pragma unroll
                for (int kk = 0; kk < 64; kk++) {
                    const ulonglong2 hv =
                        *(const ulonglong2*)&slot[1024 + (q * 64 + kk) * 4];
                    const ull w0 = pack2(wA0[kk]), w1 = pack2(wA1[kk]);
                    fma2(a00, hv.x, w0); fma2(a01, hv.y, w0);
                    fma2(a10, hv.x, w1); fma2(a11, hv.y, w1);
                }
                ulonglong2 s0; s0.x = a00; s0.y = a01;
                ulonglong2 s1; s1.x = a10; s1.y = a11;
                *(ulonglong2*)&smem[RA_OFF + ((q * 32 + lane) * 2 + 0) * 4] = s0;
                *(ulonglong2*)&smem[RA_OFF + ((q * 32 + lane) * 2 + 1) * 4] = s1;
            }
            if (act1) {                    // L1 tail: staged k [384+q*32, +32)
                const int kb = 384 + q * 32;
                ull a00 = 0ull, a01 = 0ull, a10 = 0ull, a11 = 0ull;
#pragma unroll
                for (int kk = 0; kk < 32; kk++) {
                    const int k = kb + kk;
                    const ulonglong2 hv = *(const ulonglong2*)&slot[k * 4];
                    const float2 wv = *(const float2*)&smem[WB_OFF + k * 64 + pp0];
                    const ull w0 = pack2(wv.x), w1 = pack2(wv.y);
                    fma2(a00, hv.x, w0); fma2(a01, hv.y, w0);
                    fma2(a10, hv.x, w1); fma2(a11, hv.y, w1);
                }
                ulonglong2 s0; s0.x = a00; s0.y = a01;
                ulonglong2 s1; s1.x = a10; s1.y = a11;
                *(ulonglong2*)&smem[RT_OFF + ((q * 32 + lane) * 2 + 0) * 4] = s0;
                *(ulonglong2*)&smem[RT_OFF + ((q * 32 + lane) * 2 + 1) * 4] = s1;
            }
        }
        __syncthreads();

        // ---- gates ----
        const bool gact = glayer ? act1 : act0;
        if (gact) {
            const int lh = gj >> 1, pc = gj & 1;
            float sh = 0.f, st = 0.f;
            if (!glayer) {
#pragma unroll
                for (int q = 0; q < 4; q++) {
                    sh += smem[RA_OFF + ((q * 32 + lh) * 2 + pc) * 4 + gr];
                    st += smem[RA_OFF + ((q * 32 + 16 + lh) * 2 + pc) * 4 + gr];
                }
                sh += xh; st += xt;
            } else {
#pragma unroll
                for (int q = 0; q < 4; q++) {
                    sh += smem[RB_OFF + ((q * 32 + lh) * 2 + pc) * 4 + gr]
                        + smem[RT_OFF + ((q * 32 + lh) * 2 + pc) * 4 + gr];
                    st += smem[RB_OFF + ((q * 32 + 16 + lh) * 2 + pc) * 4 + gr]
                        + smem[RT_OFF + ((q * 32 + 16 + lh) * 2 + pc) * 4 + gr];
                }
                sh += gbh; st += gbt;
            }
            const int t = glayer ? (i - 1) : i;
            const float tg = 1.f / (1.f + __expf(-st));
            const float cg = 1.f / (1.f + __expf(-tg));   // bug-faithful
            const float sv = tanhf(sh) * tg + hcur * cg;
            hcur = (t < glen) ? sv : hcur;
            smem[SG_OFF + glayer * 128 + gj * 4 + gr] = hcur;
            if (glayer)
                out1[((size_t)(i - 1) * BATCH + dom4 + gr) * HID + c0 + gj] = hcur;
        }
        __syncthreads();

        // ---- broadcast: each thread pushes 2 chunks to one peer ----
        {
            const int peer = tid & 7;
            const int ch = tid >> 3;       // 0..31 = local col j
            const float4 v0 = *(const float4*)&smem[SG_OFF + ch * 4];        // L0
            const float4 v1 = *(const float4*)&smem[SG_OFF + 128 + ch * 4];  // L1
            const uint32_t sbase = (uint32_t)(HS_OFF + ws * 2048);
            stv4_cluster(rbase[peer] + (sbase + 1024 + (c0 + ch) * 4) * 4, v0);
            stv4_cluster(rbase[peer] + (sbase + (c0 + ch) * 4) * 4, v1);
        }
        asm volatile("fence.acq_rel.cluster;" ::: "memory");
        __syncthreads();
        if (tid < 8)
            st_flag_release(rbase[tid] + (uint32_t)(FL_OFF + rank) * 4,
                            (unsigned)(i + 1));
    }

    // ---- epilogue: hn + frozen-tail fill ----
    if (!glayer) {
        hn[(dom4 + gr) * HID + c0 + gj] = hcur;
    } else {
        hn[BATCH * HID + (dom4 + gr) * HID + c0 + gj] = hcur;
        smem[RB_OFF + gr * 32 + gj] = hcur;    // transpose stage for fill
    }
    __syncthreads();
    {
        const int nf4 = (T_LEN - Ld) * 32;     // (t, rr(4), j4(8)) float4 units
        for (int idx = tid; idx < nf4; idx += 256) {
            const int t  = Ld + (idx >> 5);
            const int rr = (idx >> 3) & 3;
            const int j4 = idx & 7;
            *(float4*)&out1[((size_t)t * BATCH + dom4 + rr) * HID + c0 + j4 * 4] =
                *(const float4*)&smem[RB_OFF + rr * 32 + j4 * 4];
        }
    }
    cluster_bar();                             // no exit while peers may push
    if (bid == 0 && tid == 0) *(volatile unsigned*)&g_run = R + 1u;
}

// ---------------------------------------------------------------------------
extern "C" void kernel_launch(void* const* d_in, const int* in_sizes, int n_in,
                              void* d_out, int out_size) {
    const float* input  = (const float*)d_in[0];
    const int*   length = (const int*)d_in[1];
    const float* Wih0   = (const float*)d_in[2];
    const float* Whh0   = (const float*)d_in[3];
    const float* b0     = (const float*)d_in[4];
    const float* Wih1   = (const float*)d_in[5];
    const float* Whh1   = (const float*)d_in[6];
    const float* b1     = (const float*)d_in[7];

    float* out1 = (float*)d_out;
    float* hn   = (float*)d_out + (size_t)T_LEN * BATCH * HID;

    static bool attr_set = false;
    if (!attr_set) {
        cudaFuncSetAttribute(fused_all, cudaFuncAttributeMaxDynamicSharedMemorySize,
                             SMEM_BYTES);
        attr_set = true;
    }

    fused_all<<<NTOT, 256, SMEM_BYTES>>>(
        input, Whh0, Whh1, Wih0, Wih1, b0, b1, length, out1, hn);
}

// round 17
// speedup vs baseline: 1.2807x; 1.2807x over previous
#include <cuda_runtime.h>
#include <cstdint>

#define T_LEN 2048
#define BATCH 32
#define HID   256
#define G3    768
#define NSCAN 128          // 16 domains x 8 blocks
#define NDOM  16
#define NTOT  148
#define NWORK (NTOT - NSCAN)   // 20 gemm workers
#define NTILE 8192

typedef unsigned long long ull;

// smem float offsets (scan CTA)
#define WL1_OFF 0          // L1 weights [512 staged-k][64 pc]   = 32768 (128KB)
#define HS_OFF  32768      // staged h [512 k][2 r]              = 1024
#define RED_OFF 33792      // partials [2 gl][4 q][64 pc][2 r]   = 1024
#define SGS_OFF 34816      // final h1 staging [2 r][32 j]       = 64
#define SMEM_FLOATS 34880
#define SMEM_BYTES  (SMEM_FLOATS * 4)

// Exchange slots: per domain, 2-deep ring; word (k, r) = float2 {h, tag}
// float idx = k*4 + r*2.  Staged k: 0..255 = h1 cols, 256..511 = h0 cols.
__device__ __align__(16) float g_slot[NDOM * 2 * 2048];
__device__ float g_X[(size_t)T_LEN * BATCH * 512];   // [m=t*32+b][c 512]
__device__ unsigned g_tcnt[T_LEN / 2];               // 8 tiles per bx per run
__device__ unsigned g_run;                           // epoch

// ---------------------------------------------------------------------------
__device__ __forceinline__ ull pack2(float v) {
    ull r; asm("mov.b64 %0, {%1, %1};" : "=l"(r) : "f"(v)); return r;
}
__device__ __forceinline__ void fma2(ull& d, ull a, ull b) {
    asm("fma.rn.f32x2 %0, %1, %2, %0;" : "+l"(d) : "l"(a), "l"(b));
}
__device__ __forceinline__ void unpack2(ull v, float& lo, float& hi) {
    asm("mov.b64 {%0, %1}, %2;" : "=f"(lo), "=f"(hi) : "l"(v));
}
__device__ __forceinline__ float4 ldcg4v(const float* p) {
    float4 v;
    asm volatile("ld.global.cg.v4.f32 {%0,%1,%2,%3}, [%4];"
                 : "=f"(v.x), "=f"(v.y), "=f"(v.z), "=f"(v.w)
                 : "l"(p) : "memory");
    return v;
}
__device__ __forceinline__ void stcg2v(float* p, float a, float b) {
    asm volatile("st.global.cg.v2.f32 [%0], {%1,%2};"
                 :: "l"(p), "f"(a), "f"(b) : "memory");
}
__device__ __forceinline__ void poll_ge(const unsigned* addr, unsigned target) {
    unsigned v;
    do {
        asm volatile("ld.acquire.gpu.global.u32 %0, [%1];"
                     : "=r"(v) : "l"(addr) : "memory");
    } while ((int)(v - target) < 0);
}

// ---------------------------------------------------------------------------
// GEMM worker: grid-strided 64x64x256 tiles; g_X = input @ Wih0[:,:512] + b0
// ---------------------------------------------------------------------------
__device__ void gemm_worker(int wb, const float* __restrict__ A,
                            const float* __restrict__ W,
                            const float* __restrict__ bias,
                            float* smem, int Lmax)
{
    float (*As)[65] = (float(*)[65])smem;
    float (*Bs)[64] = (float(*)[64])(smem + 32 * 65);

    const int tid = threadIdx.x;
    const int tx  = tid & 15;
    const int ty  = tid >> 4;
    const int ar  = tid >> 2;
    const int ak  = (tid & 3) * 8;
    const int bk  = tid >> 3;
    const int bc  = (tid & 7) * 8;

    for (int n = wb; n < NTILE; n += NWORK) {
        const int bx = n >> 3;
        if (2 * bx >= Lmax) break;
        const int m0 = bx * 64;
        const int n0 = (n & 7) * 64;

        ull acc2[4][2];
#pragma unroll
        for (int i = 0; i < 4; i++) { acc2[i][0] = 0ull; acc2[i][1] = 0ull; }

        for (int k0 = 0; k0 < 256; k0 += 32) {
            float4 a0  = *(const float4*)&A[(size_t)(m0 + ar) * 256 + k0 + ak];
            float4 a1  = *(const float4*)&A[(size_t)(m0 + ar) * 256 + k0 + ak + 4];
            float4 b0v = *(const float4*)&W[(size_t)(k0 + bk) * G3 + n0 + bc];
            float4 b1v = *(const float4*)&W[(size_t)(k0 + bk) * G3 + n0 + bc + 4];

            As[ak + 0][ar] = a0.x; As[ak + 1][ar] = a0.y;
            As[ak + 2][ar] = a0.z; As[ak + 3][ar] = a0.w;
            As[ak + 4][ar] = a1.x; As[ak + 5][ar] = a1.y;
            As[ak + 6][ar] = a1.z; As[ak + 7][ar] = a1.w;
            *(float4*)&Bs[bk][bc]     = b0v;
            *(float4*)&Bs[bk][bc + 4] = b1v;
            __syncthreads();

#pragma unroll
            for (int kk = 0; kk < 32; kk++) {
                const ulonglong2 bq = *(const ulonglong2*)&Bs[kk][ty * 4];
#pragma unroll
                for (int ri = 0; ri < 4; ri++) {
                    const ull av = pack2(As[kk][tx * 4 + ri]);
                    fma2(acc2[ri][0], bq.x, av);
                    fma2(acc2[ri][1], bq.y, av);
                }
            }
            __syncthreads();
        }

        const float4 bv = *(const float4*)&bias[n0 + ty * 4];
#pragma unroll
        for (int ri = 0; ri < 4; ri++) {
            float4 v;
            unpack2(acc2[ri][0], v.x, v.y);
            unpack2(acc2[ri][1], v.z, v.w);
            v.x += bv.x; v.y += bv.y; v.z += bv.z; v.w += bv.w;
            *(float4*)&g_X[(size_t)(m0 + tx * 4 + ri) * 512 + n0 + ty * 4] = v;
        }

        __threadfence();
        __syncthreads();
        if (tid == 0) {
            asm volatile("red.release.gpu.global.add.u32 [%0], %1;"
                         :: "l"(&g_tcnt[bx]), "r"(1u) : "memory");
        }
    }
}

// ---------------------------------------------------------------------------
// ONE kernel, 148 blocks (1/SM), no clusters.
// blocks 0..127: scan. domain = 2 batch rows (16 domains x 8 blocks); block
//   owns 32 h-cols of both layers. Round i: L0 computes h0(i) [i<Ld],
//   L1 computes h1(i-1) [i>=1]. Exchange: tag-fused (h,tag) float2 words in
//   g_slot ring (depth 2), validated by __syncthreads_and retry loop.
//   Tags = R*4096 + 1 + i  (the +1 avoids colliding with zero-init memory).
//   warps 0-3 = L1 dot (smem weights), warps 4-7 = L0 dot (reg weights).
// blocks 128..147: gemm workers.
// ---------------------------------------------------------------------------
__global__ __launch_bounds__(256, 1) void fused_all(
    const float* __restrict__ input,
    const float* __restrict__ Whh0,
    const float* __restrict__ Whh1,
    const float* __restrict__ Wih0,
    const float* __restrict__ Wih1,
    const float* __restrict__ b0,
    const float* __restrict__ b1,
    const int*   __restrict__ length,
    float* __restrict__ out1,
    float* __restrict__ hn)
{
    extern __shared__ float smem[];
    const int bid = blockIdx.x;
    const int tid = threadIdx.x;

    int Lmax = 0;
#pragma unroll 8
    for (int r = 0; r < BATCH; r++) Lmax = max(Lmax, length[r]);

    if (bid >= NSCAN) {
        gemm_worker(bid - NSCAN, input, Wih0, b0, smem, Lmax);
        return;
    }

    float* wl1 = smem + WL1_OFF;
    float* hs  = smem + HS_OFF;
    float* red = smem + RED_OFF;
    float* sgs = smem + SGS_OFF;

    const int d    = bid >> 3;
    const int rank = bid & 7;
    const int c0   = rank * 32;
    const int dom2 = d * 2;

    const int Ld = max(length[dom2], length[dom2 + 1]);

    const unsigned R    = *(volatile unsigned*)&g_run;
    const unsigned base = R * 4096u + 1u;     // +1: never matches zero-init
    const unsigned tb   = R * 8u;

    // ---- load L1 weights into smem: wl1[staged k][64 pc] ----
    for (int idx = tid; idx < 32768; idx += 256) {
        const int k = idx >> 6, pc = idx & 63;
        const int col = (pc < 32) ? (c0 + pc) : (256 + c0 + pc - 32);
        wl1[idx] = (k < 256) ? Whh1[(size_t)k * G3 + col]
                             : Wih1[(size_t)(k - 256) * G3 + col];
    }

    const int wid  = tid >> 5;
    const int lane = tid & 31;
    const int q    = wid & 3;

    // ---- L0 weights in registers (warps 4-7): 2 precols x 64 k ----
    float wA0[64], wA1[64];
    if (wid >= 4) {
        const int pc0 = 2 * lane;
        const int cA0 = (pc0 < 32) ? (c0 + pc0) : (256 + c0 + pc0 - 32);
        const int cA1 = (pc0 + 1 < 32) ? (c0 + pc0 + 1) : (256 + c0 + pc0 + 1 - 32);
#pragma unroll
        for (int kk = 0; kk < 64; kk++) {
            wA0[kk] = Whh0[(size_t)(q * 64 + kk) * G3 + cA0];
            wA1[kk] = Whh0[(size_t)(q * 64 + kk) * G3 + cA1];
        }
    }

    // ---- gate identity: tid<128; ggl=0 -> L0, 1 -> L1 ----
    const bool isg = (tid < 128);
    const int  ggl = tid >> 6;             // valid when isg
    const int  grem = tid & 63;
    const int  gjj = grem >> 1;            // local h-col 0..31
    const int  grr = grem & 1;             // domain row 0..1
    const int  glen = length[dom2 + grr];
    float gbh = 0.f, gbt = 0.f;
    if (isg && ggl == 1) { gbh = b1[c0 + gjj]; gbt = b1[256 + c0 + gjj]; }
    float hcur = 0.f;
    int rdy = 0;

    float* slots = g_slot + d * 2 * 2048;

    __syncthreads();   // wl1 ready

    for (int i = 0; i <= Ld; i++) {
        const bool a0 = (i < Ld);
        const bool a1 = (i >= 1);

        // ---- gemm progress (thread 255, concurrent with validate) ----
        if (tid == 255 && a0 && (i >> 1) >= rdy) {
            poll_ge(&g_tcnt[i >> 1], tb + 8u);
            rdy = (i >> 1) + 1;
        }

        // ---- validate + stage slot ((i-1)&1): tag-fused retry loop ----
        if (i > 0) {
            const float* slot = slots + ((i + 1) & 1) * 2048;
            const unsigned tagv = base + (unsigned)(i - 1);
            const int k1 = tid, k2 = tid + 256;
            for (;;) {
                const float4 v0 = ldcg4v(slot + k1 * 4);
                const float4 v1 = ldcg4v(slot + k2 * 4);
                const int ok = (__float_as_uint(v0.y) == tagv)
                             & (__float_as_uint(v0.w) == tagv)
                             & (__float_as_uint(v1.y) == tagv)
                             & (__float_as_uint(v1.w) == tagv);
                hs[k1 * 2 + 0] = v0.x; hs[k1 * 2 + 1] = v0.z;
                hs[k2 * 2 + 0] = v1.x; hs[k2 * 2 + 1] = v1.z;
                if (__syncthreads_and(ok)) break;
            }
        } else {
            __syncthreads();
        }

        // ---- L0 x-term prefetch (after tcnt confirmed by barrier) ----
        float xh = 0.f, xt = 0.f;
        if (isg && ggl == 0 && a0) {
            const size_t m = (size_t)i * BATCH + dom2 + grr;
            xh = __ldg(&g_X[m * 512 + c0 + gjj]);
            xt = __ldg(&g_X[m * 512 + 256 + c0 + gjj]);
        }

        // ---- dots (skip entirely at i==0) ----
        if (i > 0) {
            if (wid < 4) {
                if (a1) {   // L1: staged k in [q*128, q*128+128)
                    ull acc0 = 0ull, acc1 = 0ull;
                    const int kb = q * 128;
#pragma unroll 16
                    for (int kk = 0; kk < 128; kk++) {
                        const int k = kb + kk;
                        const ull hv = *(const ull*)&hs[k * 2];
                        const float2 wv = *(const float2*)&wl1[k * 64 + 2 * lane];
                        fma2(acc0, hv, pack2(wv.x));
                        fma2(acc1, hv, pack2(wv.y));
                    }
                    ulonglong2 s2; s2.x = acc0; s2.y = acc1;
                    *(ulonglong2*)&red[((4 + q) * 64 + 2 * lane) * 2] = s2;
                }
            } else {
                if (a0) {   // L0: staged k in [256+q*64, +64)
                    ull acc0 = 0ull, acc1 = 0ull;
                    const int kb = 256 + q * 64;
#pragma unroll 16
                    for (int kk = 0; kk < 64; kk++) {
                        const ull hv = *(const ull*)&hs[(kb + kk) * 2];
                        fma2(acc0, hv, pack2(wA0[kk]));
                        fma2(acc1, hv, pack2(wA1[kk]));
                    }
                    ulonglong2 s2; s2.x = acc0; s2.y = acc1;
                    *(ulonglong2*)&red[(q * 64 + 2 * lane) * 2] = s2;
                }
            }
        }
        __syncthreads();

        // ---- gates + publish ----
        float* wslot = slots + (i & 1) * 2048;
        if (isg) {
            const bool gact = ggl ? a1 : a0;
            if (gact) {
                float sh, st;
                if (i == 0) {            // L0 only: no recurrent term
                    sh = xh; st = xt;
                } else {
                    sh = 0.f; st = 0.f;
#pragma unroll
                    for (int qq = 0; qq < 4; qq++) {
                        sh += red[((ggl * 4 + qq) * 64 + gjj) * 2 + grr];
                        st += red[((ggl * 4 + qq) * 64 + 32 + gjj) * 2 + grr];
                    }
                    sh += (ggl ? gbh : xh);
                    st += (ggl ? gbt : xt);
                }
                const int t = ggl ? (i - 1) : i;
                const float tg = 1.f / (1.f + __expf(-st));
                const float cg = 1.f / (1.f + __expf(-tg));   // bug-faithful
                const float sv = tanhf(sh) * tg + hcur * cg;
                hcur = (t < glen) ? sv : hcur;
                const int ks = ggl ? (c0 + gjj) : (256 + c0 + gjj);
                stcg2v(wslot + ks * 4 + grr * 2, hcur,
                       __uint_as_float(base + (unsigned)i));
                if (ggl)
                    out1[((size_t)(i - 1) * BATCH + dom2 + grr) * HID
                         + c0 + gjj] = hcur;
            } else if (ggl == 1 && i == 0) {
                // seed h1 zeros with round-0 tag (validation completeness)
                stcg2v(wslot + (c0 + gjj) * 4 + grr * 2, 0.f,
                       __uint_as_float(base));
            }
        }
        // no barrier here: next round's validate loop orders everything
    }

    // ---- epilogue: hn + frozen-tail fill ----
    if (isg) {
        if (ggl == 0) {
            hn[(dom2 + grr) * HID + c0 + gjj] = hcur;
        } else {
            hn[BATCH * HID + (dom2 + grr) * HID + c0 + gjj] = hcur;
            sgs[grr * 32 + gjj] = hcur;
        }
    }
    __syncthreads();
    {
        const int nf4 = (T_LEN - Ld) * 2 * 8;   // (t, r(2), j4(8)) float4 units
        for (int idx = tid; idx < nf4; idx += 256) {
            const int t  = Ld + (idx >> 4);
            const int rr = (idx >> 3) & 1;
            const int j4 = idx & 7;
            *(float4*)&out1[((size_t)t * BATCH + dom2 + rr) * HID + c0 + j4 * 4] =
                *(const float4*)&sgs[rr * 32 + j4 * 4];
        }
    }
    if (bid == 0 && tid == 0) *(volatile unsigned*)&g_run = R + 1u;
}

// ---------------------------------------------------------------------------
extern "C" void kernel_launch(void* const* d_in, const int* in_sizes, int n_in,
                              void* d_out, int out_size) {
    const float* input  = (const float*)d_in[0];
    const int*   length = (const int*)d_in[1];
    const float* Wih0   = (const float*)d_in[2];
    const float* Whh0   = (const float*)d_in[3];
    const float* b0     = (const float*)d_in[4];
    const float* Wih1   = (const float*)d_in[5];
    const float* Whh1   = (const float*)d_in[6];
    const float* b1     = (const float*)d_in[7];

    float* out1 = (float*)d_out;
    float* hn   = (float*)d_out + (size_t)T_LEN * BATCH * HID;

    static bool attr_set = false;
    if (!attr_set) {
        cudaFuncSetAttribute(fused_all, cudaFuncAttributeMaxDynamicSharedMemorySize,
                             SMEM_BYTES);
        attr_set = true;
    }

    fused_all<<<NTOT, 256, SMEM_BYTES>>>(
        input, Whh0, Whh1, Wih0, Wih1, b0, b1, length, out1, hn);
}